// round 1
// baseline (speedup 1.0000x reference)
#include <cuda_runtime.h>

// Problem constants
#define T_STEPS 500
#define BATCH   1024
#define NDIM    256
#define ALPHA_F 0.995f   // 1 - 0.05/10
#define VTH_F   1.0f

// Scratch for the per-(t,b) input currents s = x_t @ w  (2 MB, L2-resident)
__device__ float g_s[T_STEPS * BATCH];

// ---------------------------------------------------------------------------
// Kernel 1: GEMV — s[row] = dot(x[row, 0:256], w)   for row in [0, T*B)
// Warp-per-row, float4 loads (each lane covers 8 elements), shfl reduce.
// Fully coalesced 512 MB stream from HBM; this kernel IS the roofline.
// ---------------------------------------------------------------------------
__global__ void __launch_bounds__(256) lif_dot_kernel(
    const float* __restrict__ x, const float* __restrict__ w)
{
    __shared__ float ws[NDIM];
    const int tid = threadIdx.x;
    ws[tid] = w[tid];            // blockDim.x == 256 == NDIM
    __syncthreads();

    const int warp = tid >> 5;
    const int lane = tid & 31;
    const long long row = (long long)blockIdx.x * 8 + warp;   // 8 rows / block
    if (row >= (long long)T_STEPS * BATCH) return;

    const float4* xr = reinterpret_cast<const float4*>(x + row * NDIM);
    const float4* wr = reinterpret_cast<const float4*>(ws);

    // elements [lane*4, lane*4+4) and [128 + lane*4, ...)
    float4 a0 = xr[lane];
    float4 a1 = xr[lane + 32];
    float4 w0 = wr[lane];
    float4 w1 = wr[lane + 32];

    float acc = a0.x * w0.x + a0.y * w0.y + a0.z * w0.z + a0.w * w0.w
              + a1.x * w1.x + a1.y * w1.y + a1.z * w1.z + a1.w * w1.w;

    #pragma unroll
    for (int off = 16; off > 0; off >>= 1)
        acc += __shfl_xor_sync(0xffffffffu, acc, off);

    if (lane == 0) g_s[row] = acc;
}

// ---------------------------------------------------------------------------
// Kernel 2: sequential LIF scan over T per batch element.
//   v <- alpha*v + s_t - z_prev ;  z <- (v - 1 > 0)
// 1024 threads, coalesced loads of g_s (stride BATCH per step), 4-wide manual
// prefetch so the 4 independent loads issue before the dependent FMA chain.
// ---------------------------------------------------------------------------
__global__ void __launch_bounds__(256) lif_scan_kernel(float* __restrict__ out)
{
    const int b = blockIdx.x * blockDim.x + threadIdx.x;   // 0..1023
    if (b >= BATCH) return;

    float* __restrict__ vout = out;                         // [T, B]
    float* __restrict__ zout = out + (long long)T_STEPS * BATCH;  // [T, B]

    float v = 0.0f, z = 0.0f;

    #pragma unroll 1
    for (int t = 0; t < T_STEPS; t += 4) {
        // independent loads — issue all 4 before the dependent chain
        const float s0 = g_s[(t + 0) * BATCH + b];
        const float s1 = g_s[(t + 1) * BATCH + b];
        const float s2 = g_s[(t + 2) * BATCH + b];
        const float s3 = g_s[(t + 3) * BATCH + b];

        v = ALPHA_F * v + s0 - z;  z = (v - VTH_F > 0.0f) ? 1.0f : 0.0f;
        vout[(t + 0) * BATCH + b] = v;  zout[(t + 0) * BATCH + b] = z;

        v = ALPHA_F * v + s1 - z;  z = (v - VTH_F > 0.0f) ? 1.0f : 0.0f;
        vout[(t + 1) * BATCH + b] = v;  zout[(t + 1) * BATCH + b] = z;

        v = ALPHA_F * v + s2 - z;  z = (v - VTH_F > 0.0f) ? 1.0f : 0.0f;
        vout[(t + 2) * BATCH + b] = v;  zout[(t + 2) * BATCH + b] = z;

        v = ALPHA_F * v + s3 - z;  z = (v - VTH_F > 0.0f) ? 1.0f : 0.0f;
        vout[(t + 3) * BATCH + b] = v;  zout[(t + 3) * BATCH + b] = z;
    }
}

// ---------------------------------------------------------------------------
extern "C" void kernel_launch(void* const* d_in, const int* in_sizes, int n_in,
                              void* d_out, int out_size)
{
    const float* x = (const float*)d_in[0];   // [T, B, N] fp32
    const float* w = (const float*)d_in[1];   // [N] fp32
    float* out = (float*)d_out;               // [2, T, B] fp32 (v then z)

    const long long n_rows = (long long)T_STEPS * BATCH;   // 512000
    const int dot_blocks = (int)((n_rows + 7) / 8);        // 8 rows per block

    lif_dot_kernel<<<dot_blocks, 256>>>(x, w);
    lif_scan_kernel<<<(BATCH + 255) / 256, 256>>>(out);
}

// round 2
// speedup vs baseline: 1.5044x; 1.5044x over previous
#include <cuda_runtime.h>

// Problem constants
#define T_STEPS 500
#define BATCH   1024
#define NDIM    256
#define ALPHA_F 0.995f   // 1 - 0.05/10
#define VTH_F   1.0f

// Scratch for the per-(t,b) input currents s = x_t @ w  (2 MB, L2-resident)
__device__ float g_s[T_STEPS * BATCH];

// ---------------------------------------------------------------------------
// Kernel 1: GEMV — s[row] = dot(x[row, 0:256], w)   for row in [0, T*B)
// Warp-per-row, float4 loads, shfl reduce. This kernel IS the HBM roofline
// (512 MB stream, measured ~7.1 TB/s). Unchanged from R1.
// ---------------------------------------------------------------------------
__global__ void __launch_bounds__(256) lif_dot_kernel(
    const float* __restrict__ x, const float* __restrict__ w)
{
    __shared__ float ws[NDIM];
    const int tid = threadIdx.x;
    ws[tid] = w[tid];            // blockDim.x == 256 == NDIM
    __syncthreads();

    const int warp = tid >> 5;
    const int lane = tid & 31;
    const long long row = (long long)blockIdx.x * 8 + warp;   // 8 rows / block
    if (row >= (long long)T_STEPS * BATCH) return;

    const float4* xr = reinterpret_cast<const float4*>(x + row * NDIM);
    const float4* wr = reinterpret_cast<const float4*>(ws);

    float4 a0 = xr[lane];
    float4 a1 = xr[lane + 32];
    float4 w0 = wr[lane];
    float4 w1 = wr[lane + 32];

    float acc = a0.x * w0.x + a0.y * w0.y + a0.z * w0.z + a0.w * w0.w
              + a1.x * w1.x + a1.y * w1.y + a1.z * w1.z + a1.w * w1.w;

    #pragma unroll
    for (int off = 16; off > 0; off >>= 1)
        acc += __shfl_xor_sync(0xffffffffu, acc, off);

    if (lane == 0) g_s[row] = acc;
}

// ---------------------------------------------------------------------------
// Kernel 2: sequential LIF scan.
// R2 changes vs R1 (which ran at 80us, issue=5.4%, pure exposed L2 latency):
//   * __ldg() on g_s -> read-only path, breaks the compiler's assumed
//     aliasing with the output stores that was serializing load groups
//     behind stores.
//   * 20-deep register double-buffer: next group's 20 loads are issued
//     before processing the current group (~240 cycles of dependent-chain
//     work covers one L2-hit latency).
//   * 16 blocks x 64 threads: spreads stores/MLP over 16 SMs.
// ---------------------------------------------------------------------------
#define GROUP 20            // 500 % 20 == 0
#define SCAN_BLOCKS 16
#define SCAN_TPB (BATCH / SCAN_BLOCKS)   // 64

__global__ void __launch_bounds__(SCAN_TPB) lif_scan_kernel(float* __restrict__ out)
{
    const int b = blockIdx.x * SCAN_TPB + threadIdx.x;   // 0..1023

    float* __restrict__ vout = out;                                 // [T, B]
    float* __restrict__ zout = out + (long long)T_STEPS * BATCH;    // [T, B]

    float v = 0.0f, z = 0.0f;
    float cur[GROUP], nxt[GROUP];

    // prime the pipeline: group 0
    #pragma unroll
    for (int i = 0; i < GROUP; ++i)
        cur[i] = __ldg(&g_s[i * BATCH + b]);

    #pragma unroll 1
    for (int t = 0; t < T_STEPS; t += GROUP) {
        const int tn = t + GROUP;
        if (tn < T_STEPS) {
            // issue next group's independent loads before the dependent chain
            #pragma unroll
            for (int i = 0; i < GROUP; ++i)
                nxt[i] = __ldg(&g_s[(tn + i) * BATCH + b]);
        }

        #pragma unroll
        for (int i = 0; i < GROUP; ++i) {
            v = ALPHA_F * v + cur[i] - z;          // fmaf + sub
            z = (v > VTH_F) ? 1.0f : 0.0f;         // (v - vth > 0)
            vout[(t + i) * BATCH + b] = v;
            zout[(t + i) * BATCH + b] = z;
        }

        #pragma unroll
        for (int i = 0; i < GROUP; ++i)
            cur[i] = nxt[i];
    }
}

// ---------------------------------------------------------------------------
extern "C" void kernel_launch(void* const* d_in, const int* in_sizes, int n_in,
                              void* d_out, int out_size)
{
    const float* x = (const float*)d_in[0];   // [T, B, N] fp32
    const float* w = (const float*)d_in[1];   // [N] fp32
    float* out = (float*)d_out;               // [2, T, B] fp32 (v then z)

    const long long n_rows = (long long)T_STEPS * BATCH;   // 512000
    const int dot_blocks = (int)((n_rows + 7) / 8);        // 8 rows per block

    lif_dot_kernel<<<dot_blocks, 256>>>(x, w);
    lif_scan_kernel<<<SCAN_BLOCKS, SCAN_TPB>>>(out);
}